// round 13
// baseline (speedup 1.0000x reference)
#include <cuda_runtime.h>
#include <cuda_fp16.h>
#include <cstdint>

#define HID 768
#define TSEQ 1024
#define BATCH 64
#define NCTA 128

// ---------------- device scratch ----------------
// xp scratch: [d][t][us(64)][b(64)][48] fp32 (1.61 GB) — CTA-contiguous slices
__device__ float g_xp[402653184];
__device__ __half g_x16[64 * 1024 * 512];
__device__ __half g_wx16[6144 * 512];
__device__ __half g_h16[2 * 2 * BATCH * HID];   // h double buffer fp16
__device__ float g_hc[4 * BATCH * HID];         // hf, cf, hb, cb fp32
// tree barrier state (128B padding per counter)
__device__ unsigned g_sub[2][8 * 32];
__device__ unsigned g_mid[2 * 32];
__device__ unsigned g_gen2[2 * 32];

__global__ void init_kernel() {
    int i = threadIdx.x;
    if (i < 8 * 32) { g_sub[0][i] = 0; g_sub[1][i] = 0; }
    if (i < 2 * 32) { g_mid[i] = 0; g_gen2[i] = 0; }
}

// ---------------- generic helpers ----------------
__device__ __forceinline__ void cp16(void* sdst, const void* gsrc) {
    unsigned sa = (unsigned)__cvta_generic_to_shared(sdst);
    asm volatile("cp.async.cg.shared.global [%0], [%1], 16;" :: "r"(sa), "l"(gsrc));
}
__device__ __forceinline__ void cp_commit() { asm volatile("cp.async.commit_group;"); }
template <int N> __device__ __forceinline__ void cp_wait() {
    asm volatile("cp.async.wait_group %0;" :: "n"(N));
}
__device__ __forceinline__ void ldsm4(unsigned& r0, unsigned& r1, unsigned& r2,
                                      unsigned& r3, const void* p) {
    unsigned a = (unsigned)__cvta_generic_to_shared(p);
    asm volatile("ldmatrix.sync.aligned.m8n8.x4.shared.b16 {%0,%1,%2,%3}, [%4];"
                 : "=r"(r0), "=r"(r1), "=r"(r2), "=r"(r3) : "r"(a));
}
__device__ __forceinline__ unsigned ldcg32(const void* p) {
    unsigned v;
    asm volatile("ld.global.cg.u32 %0, [%1];" : "=r"(v) : "l"(p));
    return v;
}
__device__ __forceinline__ void mma16(float* acc, unsigned a0, unsigned a1,
                                      unsigned a2, unsigned a3, unsigned b0, unsigned b1) {
    asm volatile(
        "mma.sync.aligned.m16n8k16.row.col.f32.f16.f16.f32 "
        "{%0,%1,%2,%3},{%4,%5,%6,%7},{%8,%9},{%0,%1,%2,%3};"
        : "+f"(acc[0]), "+f"(acc[1]), "+f"(acc[2]), "+f"(acc[3])
        : "r"(a0), "r"(a1), "r"(a2), "r"(a3), "r"(b0), "r"(b1));
}
__device__ __forceinline__ float tanhapx(float x) {
    float y;
    asm("tanh.approx.f32 %0, %1;" : "=f"(y) : "f"(x));
    return y;
}
__device__ __forceinline__ float sigmapx(float x) {
    return 0.5f + 0.5f * tanhapx(0.5f * x);
}
// ---- tree grid barrier per direction (64 CTAs = 8 groups of 8) ----
__device__ __forceinline__ void garrive(int d, int cid) {
    __threadfence();
    __syncthreads();
    if (threadIdx.x == 0) {
        int gidx = (cid >> 3) & 7;
        unsigned a = atomicAdd(&g_sub[d][gidx * 32], 1u);
        if (a == 7u) {
            g_sub[d][gidx * 32] = 0;
            __threadfence();
            unsigned b = atomicAdd(&g_mid[d * 32], 1u);
            if (b == 7u) {
                g_mid[d * 32] = 0;
                __threadfence();
                atomicAdd(&g_gen2[d * 32], 1u);
            }
        }
    }
}
__device__ __forceinline__ void gwait(int d, unsigned target) {
    if (threadIdx.x == 0) {
        unsigned v;
        do {
            asm volatile("ld.acquire.gpu.u32 %0, [%1];" : "=r"(v) : "l"(&g_gen2[d * 32]));
        } while (v < target);
    }
    __syncthreads();
}

// ---------------- merged fp32 -> fp16 conversion (X, Wxf, Wxb in one launch) -----
#define CONV_N1 8388608
#define CONV_N2 393216
__global__ __launch_bounds__(1024) void conv_kernel(
    const float4* __restrict__ X, const float4* __restrict__ Wxf,
    const float4* __restrict__ Wxb)
{
    int i = blockIdx.x * 1024 + threadIdx.x;
    const float4* s;
    __half2* dbase;
    int li;
    if (i < CONV_N1) {
        s = X; dbase = (__half2*)g_x16; li = i;
    } else if (i < CONV_N1 + CONV_N2) {
        s = Wxf; dbase = (__half2*)g_wx16; li = i - CONV_N1;
    } else if (i < CONV_N1 + 2 * CONV_N2) {
        s = Wxb; dbase = (__half2*)g_wx16 + 2 * CONV_N2; li = i - CONV_N1 - CONV_N2;
    } else return;
    float4 v = s[li];
    dbase[2 * li + 0] = __floats2half2_rn(v.x, v.y);
    dbase[2 * li + 1] = __floats2half2_rn(v.z, v.w);
}

// ================= Phase A: xp = x @ [Wxf;Wxb]^T + bias (fp16 mma.sync) ===========
__global__ __launch_bounds__(256, 2) void xproj_kernel(
    const float* __restrict__ bf, const float* __restrict__ bb)
{
    extern __shared__ __half sm16[];
    __half* As = sm16;
    __half* Bs = sm16 + 2 * 128 * 40;
    const int tid = threadIdx.x;
    const int bn = blockIdx.x, bm = blockIdx.y;
    const int warp = tid >> 5, lane = tid & 31;
    const int wm = warp >> 1, wn = warp & 1;
    const int gq = lane >> 2, tig = lane & 3;
    const int lrow = lane & 15, lcol = (lane >> 4) << 3;

    auto stage = [&](int buf, int k0) {
        __half* Ad = As + buf * (128 * 40);
        __half* Bd = Bs + buf * (64 * 40);
#pragma unroll
        for (int j = 0; j < 2; ++j) {
            int idx = j * 256 + tid;
            int r = idx >> 2, q = idx & 3;
            cp16(Ad + r * 40 + q * 8, g_x16 + (size_t)(bm * 128 + r) * 512 + k0 + q * 8);
        }
        {
            int r = tid >> 2, q = tid & 3;
            cp16(Bd + r * 40 + q * 8, g_wx16 + (size_t)(bn * 64 + r) * 512 + k0 + q * 8);
        }
        cp_commit();
    };

    float acc[2][4][4];
#pragma unroll
    for (int a = 0; a < 2; ++a)
#pragma unroll
        for (int b = 0; b < 4; ++b)
#pragma unroll
            for (int c = 0; c < 4; ++c) acc[a][b][c] = 0.f;

    stage(0, 0);
#pragma unroll 1
    for (int it = 0; it < 16; ++it) {
        if (it < 15) { stage((it + 1) & 1, (it + 1) * 32); cp_wait<1>(); }
        else { cp_wait<0>(); }
        __syncthreads();
        const __half* Ab = As + (it & 1) * (128 * 40);
        const __half* Bb = Bs + (it & 1) * (64 * 40);
#pragma unroll
        for (int k16 = 0; k16 < 2; ++k16) {
            int k0 = k16 * 16;
            unsigned a[2][4];
#pragma unroll
            for (int mt = 0; mt < 2; ++mt)
                ldsm4(a[mt][0], a[mt][1], a[mt][2], a[mt][3],
                      Ab + (wm * 32 + mt * 16 + lrow) * 40 + k0 + lcol);
#pragma unroll
            for (int np = 0; np < 2; ++np) {
                unsigned r0, r1, r2, r3;
                ldsm4(r0, r1, r2, r3,
                      Bb + (wn * 32 + np * 16 + lrow) * 40 + k0 + lcol);
                mma16(acc[0][np * 2 + 0], a[0][0], a[0][1], a[0][2], a[0][3], r0, r2);
                mma16(acc[0][np * 2 + 1], a[0][0], a[0][1], a[0][2], a[0][3], r1, r3);
                mma16(acc[1][np * 2 + 0], a[1][0], a[1][1], a[1][2], a[1][3], r0, r2);
                mma16(acc[1][np * 2 + 1], a[1][0], a[1][1], a[1][2], a[1][3], r1, r3);
            }
        }
        __syncthreads();
    }
    // epilogue: bias + time-reversal scatter into g_xp[d][t][us][b][48]
#pragma unroll
    for (int mt = 0; mt < 2; ++mt) {
#pragma unroll
        for (int r = 0; r < 2; ++r) {
            int m = bm * 128 + wm * 32 + mt * 16 + gq + r * 8;
            int b = m >> 10;
            int tx = m & 1023;
#pragma unroll
            for (int nt = 0; nt < 4; ++nt) {
                int n0 = bn * 64 + wn * 32 + nt * 8 + tig * 2;
                int d = (n0 >= 3072) ? 1 : 0;
                int g = n0 - d * 3072;
                int gate = g / 768;
                int unit = g - gate * 768;
                int us2 = unit / 12;
                int uu = unit - us2 * 12;
                int t = d ? (1023 - tx) : tx;
                float2 v;
                v.x = acc[mt][nt][r * 2 + 0] + (d ? bb[g] : bf[g]);
                v.y = acc[mt][nt][r * 2 + 1] + (d ? bb[g + 1] : bf[g + 1]);
                size_t addr = (((size_t)(d * 1024 + t) * 64 + us2) * 64 + b) * 48
                            + gate * 12 + uu;
                *(float2*)(g_xp + addr) = v;
            }
        }
    }
}

// ================= Phase B: persistent recurrence, direct-cg A loads ==============
// 128 CTAs x 256 thr. CTA: d = cid>>6, us = cid&63 -> units [us*12, us*12+12).
// Warp w: mw = w&3 (16 batch rows), kp = w>>2 (K-half). Each warp: disjoint 16x384
// h slab loaded DIRECTLY from gmem via ld.global.cg (no smem staging, no staleness).
// All 6 nt (48 gate cols) per warp. smem: Wf 73728 | zbuf 2x3328f | zA 3328f | zB 3328f
#define RSMEM_TOTAL 126976
__global__ __launch_bounds__(256, 1) void recur_kernel(
    const float* __restrict__ Whf, const float* __restrict__ Whb)
{
    extern __shared__ char smraw[];
    __half2* Wf2 = (__half2*)smraw;                        // 9216 uint2 = 73728 B
    float*  zbuf = (float*)(smraw + 73728);                // 2 x 64 x 52
    float*  zA   = zbuf + 2 * 3328;
    float*  zB   = zA + 3328;

    const int tid = threadIdx.x;
    const int warp = tid >> 5, lane = tid & 31;
    const int gq = lane >> 2, tig = lane & 3;
    const int mw = warp & 3;
    const int kp = warp >> 2;
    const int cid = blockIdx.x;
    const int d = cid >> 6, us = cid & 63;
    const float* Wh = d ? Whb : Whf;

    // --- pre-arrange resident weight fragments (once): all 48 chunks x 6 nt ---
    for (int idx = tid; idx < 9216; idx += 256) {
        int c = idx / 192;            // k16 chunk 0..47
        int r = idx % 192;
        int nt = r >> 5;              // 0..5
        int ln = r & 31;
        int fq = ln >> 2, ft = ln & 3;
        int gr = nt * 8 + fq;         // gate row 0..47
        int gb = gr / 12, uu = gr % 12;
        const float* w = Wh + (size_t)(gb * 768 + us * 12 + uu) * 768 + c * 16 + ft * 2;
        Wf2[idx * 2 + 0] = __floats2half2_rn(w[0], w[1]);
        Wf2[idx * 2 + 1] = __floats2half2_rn(w[8], w[9]);
    }
    // zero h buf0 for my slice
    for (int v = tid; v < 768; v += 256) {
        int b = v / 12, uu = v % 12;
        g_h16[((size_t)(0 * 2 + d) * 64 + b) * 768 + us * 12 + uu] = __float2half(0.f);
    }
    // prefetch xp(0) into zbuf[0]
    {
        const float* xp0 = g_xp + ((size_t)(d * 1024 + 0) * 64 + us) * 3072;
#pragma unroll
        for (int j = 0; j < 3; ++j) {
            int idx = j * 256 + tid;
            int b = idx / 12, q = idx % 12;
            cp16(zbuf + b * 52 + q * 4, xp0 + b * 48 + q * 4);
        }
        cp_commit();
    }
    float cc[3];
#pragma unroll
    for (int j = 0; j < 3; ++j) cc[j] = 0.f;

    garrive(d, cid);   // h(0) published

    const uint2* Wfu = (const uint2*)Wf2;

#pragma unroll 1
    for (int t = 0; t < 1024; ++t) {
        gwait(d, (unsigned)(t + 1));   // all h(t) published
        const __half* hcur = g_h16 + (size_t)((t & 1) * 2 + d) * BATCH * HID;
        const __half* hr0 = hcur + (size_t)(mw * 16 + gq) * 768;
        const __half* hr1 = hr0 + 8 * 768;

        // --- MMA: 24 k16 chunks, A-fragments loaded directly via cg-LDG ---
        float acc[6][4];
#pragma unroll
        for (int a = 0; a < 6; ++a)
#pragma unroll
            for (int b = 0; b < 4; ++b) acc[a][b] = 0.f;

#pragma unroll 4
        for (int cnk = 0; cnk < 24; ++cnk) {
            int k0 = kp * 384 + cnk * 16 + 2 * tig;
            unsigned a0 = ldcg32(hr0 + k0);
            unsigned a1 = ldcg32(hr1 + k0);
            unsigned a2 = ldcg32(hr0 + k0 + 8);
            unsigned a3 = ldcg32(hr1 + k0 + 8);
            int c = kp * 24 + cnk;
#pragma unroll
            for (int nt = 0; nt < 6; ++nt) {
                uint2 bv = Wfu[(c * 6 + nt) * 32 + lane];
                mma16(acc[nt], a0, a1, a2, a3, bv.x, bv.y);
            }
        }

        // --- write partial sums to disjoint buffers (kp0 -> zA, kp1 -> zB) ---
        float* zo = kp ? zB : zA;
#pragma unroll
        for (int nt = 0; nt < 6; ++nt) {
            int row = mw * 16 + gq;
            int col = nt * 8 + 2 * tig;
            float2 v0; v0.x = acc[nt][0]; v0.y = acc[nt][1];
            float2 v1; v1.x = acc[nt][2]; v1.y = acc[nt][3];
            *(float2*)(zo + row * 52 + col) = v0;
            *(float2*)(zo + (row + 8) * 52 + col) = v1;
        }
        cp_wait<0>();    // xp(t) prefetch complete
        __syncthreads();

        // --- pointwise: z = xp + zA + zB; 3 (b,unit) pairs per thread ---
        int nb = (t + 1) & 1;
        __half* hdst = g_h16 + (size_t)(nb * 2 + d) * BATCH * HID;
        const float* zx = zbuf + (t & 1) * 3328;
#pragma unroll
        for (int j = 0; j < 3; ++j) {
            int idx = j * 256 + tid;
            int b = idx / 12, uu = idx % 12;
            const float* zr = zx + b * 52;
            const float* ar = zA + b * 52;
            const float* br = zB + b * 52;
            float f = sigmapx(zr[uu]      + ar[uu]      + br[uu]);
            float i = sigmapx(zr[12 + uu] + ar[12 + uu] + br[12 + uu]);
            float g = tanhapx(zr[24 + uu] + ar[24 + uu] + br[24 + uu]);
            float o = sigmapx(zr[36 + uu] + ar[36 + uu] + br[36 + uu]);
            float c = f * cc[j] + i * g;
            cc[j] = c;
            float h = o * tanhapx(c);
            hdst[(size_t)b * 768 + us * 12 + uu] = __float2half_rn(h);
            if (t == 1023) {
                int unit = us * 12 + uu;
                g_hc[((size_t)(d * 2 + 0) * 64 + b) * 768 + unit] = h;
                g_hc[((size_t)(d * 2 + 1) * 64 + b) * 768 + unit] = c;
            }
        }

        garrive(d, cid);   // h(t+1) published

        // --- prefetch xp(t+1) during barrier propagation ---
        if (t < 1023) {
            const float* xpn = g_xp + ((size_t)(d * 1024 + t + 1) * 64 + us) * 3072;
            float* zn = zbuf + ((t + 1) & 1) * 3328;
#pragma unroll
            for (int j = 0; j < 3; ++j) {
                int idx = j * 256 + tid;
                int b = idx / 12, q = idx % 12;
                cp16(zn + b * 52 + q * 4, xpn + b * 48 + q * 4);
            }
            cp_commit();
        }
    }
}

// ================= Phase C: out = [hf|hb] @ Why^T + by =================
__global__ __launch_bounds__(256) void outproj_kernel(
    const float* __restrict__ Why, const float* __restrict__ by,
    float* __restrict__ out)
{
    int w = blockIdx.x * 8 + (threadIdx.x >> 5);
    int lane = threadIdx.x & 31;
    int b = w >> 9, o = w & 511;
    const float* hf = g_hc + (size_t)b * 768;
    const float* hb = g_hc + 98304 + (size_t)b * 768;
    const float* wr = Why + (size_t)o * 1536;
    float s = 0.f;
    for (int k = lane; k < 768; k += 32) s += hf[k] * wr[k];
    for (int k = lane; k < 768; k += 32) s += hb[k] * wr[768 + k];
#pragma unroll
    for (int off = 16; off; off >>= 1) s += __shfl_xor_sync(0xffffffffu, s, off);
    if (lane == 0) out[(size_t)b * 512 + o] = s + by[o];
}

// ================= launch =================
extern "C" void kernel_launch(void* const* d_in, const int* in_sizes, int n_in,
                              void* d_out, int out_size) {
    const float* X   = (const float*)d_in[0];
    const float* Wxf = (const float*)d_in[1];
    const float* Whf = (const float*)d_in[2];
    const float* bf  = (const float*)d_in[3];
    const float* Wxb = (const float*)d_in[4];
    const float* Whb = (const float*)d_in[5];
    const float* bb  = (const float*)d_in[6];
    const float* Why = (const float*)d_in[7];
    const float* by  = (const float*)d_in[8];
    float* out = (float*)d_out;

    cudaFuncSetAttribute(xproj_kernel, cudaFuncAttributeMaxDynamicSharedMemorySize, 30720);
    cudaFuncSetAttribute(recur_kernel, cudaFuncAttributeMaxDynamicSharedMemorySize, RSMEM_TOTAL);

    init_kernel<<<1, 256>>>();
    conv_kernel<<<8960, 1024>>>((const float4*)X, (const float4*)Wxf, (const float4*)Wxb);
    xproj_kernel<<<dim3(96, 512), 256, 30720>>>(bf, bb);
    recur_kernel<<<NCTA, 256, RSMEM_TOTAL>>>(Whf, Whb);
    outproj_kernel<<<4096, 256>>>(Why, by, out);

    if (out_size >= 229376) {
        void* hc = nullptr;
        cudaGetSymbolAddress(&hc, g_hc);
        cudaMemcpyAsync(out + 32768, hc, 4 * 64 * 768 * sizeof(float),
                        cudaMemcpyDeviceToDevice, 0);
    }
}

// round 15
// speedup vs baseline: 1.1951x; 1.1951x over previous
#include <cuda_runtime.h>
#include <cuda_fp16.h>
#include <cstdint>

#define HID 768
#define TSEQ 1024
#define BATCH 64
#define NCTA 128

// ---------------- device scratch ----------------
// xp scratch: [d][t][us(64)][b(64)][48] fp32 (1.61 GB) — CTA-contiguous slices
__device__ float g_xp[402653184];
__device__ __half g_x16[64 * 1024 * 512];
__device__ __half g_wx16[6144 * 512];
__device__ __half g_h16[2 * 2 * BATCH * HID];   // h double buffer fp16
__device__ float g_hc[4 * BATCH * HID];         // hf, cf, hb, cb fp32
// tree barrier state (128B padding per counter)
__device__ unsigned g_sub[2][8 * 32];
__device__ unsigned g_mid[2 * 32];
__device__ unsigned g_gen2[2 * 32];

__global__ void init_kernel() {
    int i = threadIdx.x;
    if (i < 8 * 32) { g_sub[0][i] = 0; g_sub[1][i] = 0; }
    if (i < 2 * 32) { g_mid[i] = 0; g_gen2[i] = 0; }
}

// ---------------- generic helpers ----------------
__device__ __forceinline__ void cp16(void* sdst, const void* gsrc) {
    unsigned sa = (unsigned)__cvta_generic_to_shared(sdst);
    asm volatile("cp.async.cg.shared.global [%0], [%1], 16;" :: "r"(sa), "l"(gsrc));
}
__device__ __forceinline__ void cp_commit() { asm volatile("cp.async.commit_group;"); }
template <int N> __device__ __forceinline__ void cp_wait() {
    asm volatile("cp.async.wait_group %0;" :: "n"(N));
}
__device__ __forceinline__ void ldsm4(unsigned& r0, unsigned& r1, unsigned& r2,
                                      unsigned& r3, const void* p) {
    unsigned a = (unsigned)__cvta_generic_to_shared(p);
    asm volatile("ldmatrix.sync.aligned.m8n8.x4.shared.b16 {%0,%1,%2,%3}, [%4];"
                 : "=r"(r0), "=r"(r1), "=r"(r2), "=r"(r3) : "r"(a));
}
__device__ __forceinline__ void mma16(float* acc, unsigned a0, unsigned a1,
                                      unsigned a2, unsigned a3, unsigned b0, unsigned b1) {
    asm volatile(
        "mma.sync.aligned.m16n8k16.row.col.f32.f16.f16.f32 "
        "{%0,%1,%2,%3},{%4,%5,%6,%7},{%8,%9},{%0,%1,%2,%3};"
        : "+f"(acc[0]), "+f"(acc[1]), "+f"(acc[2]), "+f"(acc[3])
        : "r"(a0), "r"(a1), "r"(a2), "r"(a3), "r"(b0), "r"(b1));
}
__device__ __forceinline__ float tanhapx(float x) {
    float y;
    asm("tanh.approx.f32 %0, %1;" : "=f"(y) : "f"(x));
    return y;
}
__device__ __forceinline__ float sigmapx(float x) {
    return 0.5f + 0.5f * tanhapx(0.5f * x);
}
// ---- tree grid barrier per direction (64 CTAs = 8 groups of 8) ----
__device__ __forceinline__ void garrive(int d, int cid) {
    __threadfence();
    __syncthreads();
    if (threadIdx.x == 0) {
        int gidx = (cid >> 3) & 7;
        unsigned a = atomicAdd(&g_sub[d][gidx * 32], 1u);
        if (a == 7u) {
            g_sub[d][gidx * 32] = 0;
            __threadfence();
            unsigned b = atomicAdd(&g_mid[d * 32], 1u);
            if (b == 7u) {
                g_mid[d * 32] = 0;
                __threadfence();
                atomicAdd(&g_gen2[d * 32], 1u);
            }
        }
    }
}
__device__ __forceinline__ void gwait(int d, unsigned target) {
    if (threadIdx.x == 0) {
        unsigned v;
        do {
            asm volatile("ld.acquire.gpu.u32 %0, [%1];" : "=r"(v) : "l"(&g_gen2[d * 32]));
        } while (v < target);
    }
    __syncthreads();
}

// ---------------- merged fp32 -> fp16 conversion (X, Wxf, Wxb in one launch) -----
#define CONV_N1 8388608
#define CONV_N2 393216
__global__ __launch_bounds__(1024) void conv_kernel(
    const float4* __restrict__ X, const float4* __restrict__ Wxf,
    const float4* __restrict__ Wxb)
{
    int i = blockIdx.x * 1024 + threadIdx.x;
    const float4* s;
    __half2* dbase;
    int li;
    if (i < CONV_N1) {
        s = X; dbase = (__half2*)g_x16; li = i;
    } else if (i < CONV_N1 + CONV_N2) {
        s = Wxf; dbase = (__half2*)g_wx16; li = i - CONV_N1;
    } else if (i < CONV_N1 + 2 * CONV_N2) {
        s = Wxb; dbase = (__half2*)g_wx16 + 2 * CONV_N2; li = i - CONV_N1 - CONV_N2;
    } else return;
    float4 v = s[li];
    dbase[2 * li + 0] = __floats2half2_rn(v.x, v.y);
    dbase[2 * li + 1] = __floats2half2_rn(v.z, v.w);
}

// ================= Phase A: xp = x @ [Wxf;Wxb]^T + bias (fp16 mma.sync) ===========
__global__ __launch_bounds__(256, 2) void xproj_kernel(
    const float* __restrict__ bf, const float* __restrict__ bb)
{
    extern __shared__ __half sm16[];
    __half* As = sm16;
    __half* Bs = sm16 + 2 * 128 * 40;
    const int tid = threadIdx.x;
    const int bn = blockIdx.x, bm = blockIdx.y;
    const int warp = tid >> 5, lane = tid & 31;
    const int wm = warp >> 1, wn = warp & 1;
    const int gq = lane >> 2, tig = lane & 3;
    const int lrow = lane & 15, lcol = (lane >> 4) << 3;

    auto stage = [&](int buf, int k0) {
        __half* Ad = As + buf * (128 * 40);
        __half* Bd = Bs + buf * (64 * 40);
#pragma unroll
        for (int j = 0; j < 2; ++j) {
            int idx = j * 256 + tid;
            int r = idx >> 2, q = idx & 3;
            cp16(Ad + r * 40 + q * 8, g_x16 + (size_t)(bm * 128 + r) * 512 + k0 + q * 8);
        }
        {
            int r = tid >> 2, q = tid & 3;
            cp16(Bd + r * 40 + q * 8, g_wx16 + (size_t)(bn * 64 + r) * 512 + k0 + q * 8);
        }
        cp_commit();
    };

    float acc[2][4][4];
#pragma unroll
    for (int a = 0; a < 2; ++a)
#pragma unroll
        for (int b = 0; b < 4; ++b)
#pragma unroll
            for (int c = 0; c < 4; ++c) acc[a][b][c] = 0.f;

    stage(0, 0);
#pragma unroll 1
    for (int it = 0; it < 16; ++it) {
        if (it < 15) { stage((it + 1) & 1, (it + 1) * 32); cp_wait<1>(); }
        else { cp_wait<0>(); }
        __syncthreads();
        const __half* Ab = As + (it & 1) * (128 * 40);
        const __half* Bb = Bs + (it & 1) * (64 * 40);
#pragma unroll
        for (int k16 = 0; k16 < 2; ++k16) {
            int k0 = k16 * 16;
            unsigned a[2][4];
#pragma unroll
            for (int mt = 0; mt < 2; ++mt)
                ldsm4(a[mt][0], a[mt][1], a[mt][2], a[mt][3],
                      Ab + (wm * 32 + mt * 16 + lrow) * 40 + k0 + lcol);
#pragma unroll
            for (int np = 0; np < 2; ++np) {
                unsigned r0, r1, r2, r3;
                ldsm4(r0, r1, r2, r3,
                      Bb + (wn * 32 + np * 16 + lrow) * 40 + k0 + lcol);
                mma16(acc[0][np * 2 + 0], a[0][0], a[0][1], a[0][2], a[0][3], r0, r2);
                mma16(acc[0][np * 2 + 1], a[0][0], a[0][1], a[0][2], a[0][3], r1, r3);
                mma16(acc[1][np * 2 + 0], a[1][0], a[1][1], a[1][2], a[1][3], r0, r2);
                mma16(acc[1][np * 2 + 1], a[1][0], a[1][1], a[1][2], a[1][3], r1, r3);
            }
        }
        __syncthreads();
    }
    // epilogue: bias + time-reversal scatter into g_xp[d][t][us][b][48]
#pragma unroll
    for (int mt = 0; mt < 2; ++mt) {
#pragma unroll
        for (int r = 0; r < 2; ++r) {
            int m = bm * 128 + wm * 32 + mt * 16 + gq + r * 8;
            int b = m >> 10;
            int tx = m & 1023;
#pragma unroll
            for (int nt = 0; nt < 4; ++nt) {
                int n0 = bn * 64 + wn * 32 + nt * 8 + tig * 2;
                int d = (n0 >= 3072) ? 1 : 0;
                int g = n0 - d * 3072;
                int gate = g / 768;
                int unit = g - gate * 768;
                int us2 = unit / 12;
                int uu = unit - us2 * 12;
                int t = d ? (1023 - tx) : tx;
                float2 v;
                v.x = acc[mt][nt][r * 2 + 0] + (d ? bb[g] : bf[g]);
                v.y = acc[mt][nt][r * 2 + 1] + (d ? bb[g + 1] : bf[g + 1]);
                size_t addr = (((size_t)(d * 1024 + t) * 64 + us2) * 64 + b) * 48
                            + gate * 12 + uu;
                *(float2*)(g_xp + addr) = v;
            }
        }
    }
}

// ================= Phase B: persistent recurrence, fp16 mma.sync, 256 thr =========
// 128 CTAs x 256 thr. CTA: d = cid>>6, us = cid&63 -> units [us*12, us*12+12).
// Warp w: kp = w&1 (K-half), ng = (w>>1)&1 (24 gate cols), mw = w>>2 (32 batch rows).
// A staged in smem (LDSM path). Tree barrier. smem total:
// Wf 73728 + A_s 99328 + zbuf 26624 + zA 13312 + zB 13312 = 226304
#define RSMEM_TOTAL 226304
__global__ __launch_bounds__(256, 1) void recur_kernel(
    const float* __restrict__ Whf, const float* __restrict__ Whb)
{
    extern __shared__ char smraw[];
    __half2* Wf2 = (__half2*)smraw;                        // 9216 uint2 = 73728 B
    __half* A_s  = (__half*)(smraw + 73728);               // 64 x 776
    float*  zbuf = (float*)(smraw + 73728 + 99328);        // 2 x 64 x 52
    float*  zA   = zbuf + 2 * 3328;
    float*  zB   = zA + 3328;

    const int tid = threadIdx.x;
    const int warp = tid >> 5, lane = tid & 31;
    const int gq = lane >> 2, tig = lane & 3;
    const int lrow = lane & 15, lcol = (lane >> 4) << 3;
    const int kp = warp & 1;
    const int ng = (warp >> 1) & 1;
    const int mw = warp >> 2;
    const int cid = blockIdx.x;
    const int d = cid >> 6, us = cid & 63;
    const float* Wh = d ? Whb : Whf;

    // --- pre-arrange resident weight fragments (once) ---
    for (int idx = tid; idx < 9216; idx += 256) {
        int c = idx / 192;            // k16 chunk 0..47
        int r = idx % 192;
        int nt = r >> 5;              // 0..5
        int ln = r & 31;
        int fq = ln >> 2, ft = ln & 3;
        int gr = nt * 8 + fq;         // gate row 0..47
        int gb = gr / 12, uu = gr % 12;
        const float* w = Wh + (size_t)(gb * 768 + us * 12 + uu) * 768 + c * 16 + ft * 2;
        Wf2[idx * 2 + 0] = __floats2half2_rn(w[0], w[1]);
        Wf2[idx * 2 + 1] = __floats2half2_rn(w[8], w[9]);
    }
    // zero h buf0 for my slice
    for (int v = tid; v < 768; v += 256) {
        int b = v / 12, uu = v % 12;
        g_h16[((size_t)(0 * 2 + d) * 64 + b) * 768 + us * 12 + uu] = __float2half(0.f);
    }
    // prefetch xp(0) into zbuf[0]
    {
        const float* xp0 = g_xp + ((size_t)(d * 1024 + 0) * 64 + us) * 3072;
#pragma unroll
        for (int j = 0; j < 3; ++j) {
            int idx = j * 256 + tid;
            int b = idx / 12, q = idx % 12;
            cp16(zbuf + b * 52 + q * 4, xp0 + b * 48 + q * 4);
        }
        cp_commit();
    }
    float cc[3];
#pragma unroll
    for (int j = 0; j < 3; ++j) cc[j] = 0.f;

    garrive(d, cid);   // h(0) published

    const uint2* Wfu = (const uint2*)Wf2;

#pragma unroll 1
    for (int t = 0; t < 1024; ++t) {
        gwait(d, (unsigned)(t + 1));   // all h(t) published
        const __half* hcur = g_h16 + (size_t)((t & 1) * 2 + d) * BATCH * HID;

        // --- stage h: all threads, 24 cp16 each (64 x 768 halves) ---
#pragma unroll 4
        for (int j = 0; j < 24; ++j) {
            int idx = j * 256 + tid;
            int b = idx / 96, q = idx % 96;
            cp16(A_s + b * 776 + q * 8, hcur + (size_t)b * 768 + q * 8);
        }
        cp_commit();
        cp_wait<0>();    // h staged (and xp(t) prefetch from earlier)
        __syncthreads();

        // --- mainloop: 24 contiguous k16 chunks for this warp's k-half ---
        float acc[2][3][4];
#pragma unroll
        for (int a = 0; a < 2; ++a)
#pragma unroll
            for (int b = 0; b < 3; ++b)
#pragma unroll
                for (int c = 0; c < 4; ++c) acc[a][b][c] = 0.f;

#pragma unroll 2
        for (int cnk = 0; cnk < 24; ++cnk) {
            int c = kp * 24 + cnk;
            int k0 = c * 16;
            unsigned a[2][4];
#pragma unroll
            for (int mt = 0; mt < 2; ++mt)
                ldsm4(a[mt][0], a[mt][1], a[mt][2], a[mt][3],
                      A_s + (mw * 32 + mt * 16 + lrow) * 776 + k0 + lcol);
#pragma unroll
            for (int nt = 0; nt < 3; ++nt) {
                uint2 bv = Wfu[(c * 6 + ng * 3 + nt) * 32 + lane];
#pragma unroll
                for (int mt = 0; mt < 2; ++mt)
                    mma16(acc[mt][nt], a[mt][0], a[mt][1], a[mt][2], a[mt][3], bv.x, bv.y);
            }
        }

        // --- write partial sums to disjoint buffers ---
        float* zo = kp ? zB : zA;
#pragma unroll
        for (int mt = 0; mt < 2; ++mt)
#pragma unroll
            for (int nt = 0; nt < 3; ++nt) {
                int row = mw * 32 + mt * 16 + gq;
                int col = ng * 24 + nt * 8 + 2 * tig;
                float2 v0; v0.x = acc[mt][nt][0]; v0.y = acc[mt][nt][1];
                float2 v1; v1.x = acc[mt][nt][2]; v1.y = acc[mt][nt][3];
                *(float2*)(zo + row * 52 + col) = v0;
                *(float2*)(zo + (row + 8) * 52 + col) = v1;
            }
        __syncthreads();

        // --- pointwise: z = xp + zA + zB; 3 (b,unit) pairs per thread ---
        int nb = (t + 1) & 1;
        __half* hdst = g_h16 + (size_t)(nb * 2 + d) * BATCH * HID;
        const float* zx = zbuf + (t & 1) * 3328;
#pragma unroll
        for (int j = 0; j < 3; ++j) {
            int idx = j * 256 + tid;
            int b = idx / 12, uu = idx % 12;
            const float* zr = zx + b * 52;
            const float* ar = zA + b * 52;
            const float* br = zB + b * 52;
            float f = sigmapx(zr[uu]      + ar[uu]      + br[uu]);
            float i = sigmapx(zr[12 + uu] + ar[12 + uu] + br[12 + uu]);
            float g = tanhapx(zr[24 + uu] + ar[24 + uu] + br[24 + uu]);
            float o = sigmapx(zr[36 + uu] + ar[36 + uu] + br[36 + uu]);
            float c = f * cc[j] + i * g;
            cc[j] = c;
            float h = o * tanhapx(c);
            hdst[(size_t)b * 768 + us * 12 + uu] = __float2half_rn(h);
            if (t == 1023) {
                int unit = us * 12 + uu;
                g_hc[((size_t)(d * 2 + 0) * 64 + b) * 768 + unit] = h;
                g_hc[((size_t)(d * 2 + 1) * 64 + b) * 768 + unit] = c;
            }
        }

        garrive(d, cid);   // h(t+1) published (fence + sync + tree atomics)

        // --- prefetch xp(t+1) during barrier propagation ---
        if (t < 1023) {
            const float* xpn = g_xp + ((size_t)(d * 1024 + t + 1) * 64 + us) * 3072;
            float* zn = zbuf + ((t + 1) & 1) * 3328;
#pragma unroll
            for (int j = 0; j < 3; ++j) {
                int idx = j * 256 + tid;
                int b = idx / 12, q = idx % 12;
                cp16(zn + b * 52 + q * 4, xpn + b * 48 + q * 4);
            }
            cp_commit();
        }
    }
}

// ================= Phase C: out = [hf|hb] @ Why^T + by =================
__global__ __launch_bounds__(256) void outproj_kernel(
    const float* __restrict__ Why, const float* __restrict__ by,
    float* __restrict__ out)
{
    int w = blockIdx.x * 8 + (threadIdx.x >> 5);
    int lane = threadIdx.x & 31;
    int b = w >> 9, o = w & 511;
    const float* hf = g_hc + (size_t)b * 768;
    const float* hb = g_hc + 98304 + (size_t)b * 768;
    const float* wr = Why + (size_t)o * 1536;
    float s = 0.f;
    for (int k = lane; k < 768; k += 32) s += hf[k] * wr[k];
    for (int k = lane; k < 768; k += 32) s += hb[k] * wr[768 + k];
#pragma unroll
    for (int off = 16; off; off >>= 1) s += __shfl_xor_sync(0xffffffffu, s, off);
    if (lane == 0) out[(size_t)b * 512 + o] = s + by[o];
}

// ================= launch =================
extern "C" void kernel_launch(void* const* d_in, const int* in_sizes, int n_in,
                              void* d_out, int out_size) {
    const float* X   = (const float*)d_in[0];
    const float* Wxf = (const float*)d_in[1];
    const float* Whf = (const float*)d_in[2];
    const float* bf  = (const float*)d_in[3];
    const float* Wxb = (const float*)d_in[4];
    const float* Whb = (const float*)d_in[5];
    const float* bb  = (const float*)d_in[6];
    const float* Why = (const float*)d_in[7];
    const float* by  = (const float*)d_in[8];
    float* out = (float*)d_out;

    cudaFuncSetAttribute(xproj_kernel, cudaFuncAttributeMaxDynamicSharedMemorySize, 30720);
    cudaFuncSetAttribute(recur_kernel, cudaFuncAttributeMaxDynamicSharedMemorySize, RSMEM_TOTAL);

    init_kernel<<<1, 256>>>();
    conv_kernel<<<8960, 1024>>>((const float4*)X, (const float4*)Wxf, (const float4*)Wxb);
    xproj_kernel<<<dim3(96, 512), 256, 30720>>>(bf, bb);
    recur_kernel<<<NCTA, 256, RSMEM_TOTAL>>>(Whf, Whb);
    outproj_kernel<<<4096, 256>>>(Why, by, out);

    if (out_size >= 229376) {
        void* hc = nullptr;
        cudaGetSymbolAddress(&hc, g_hc);
        cudaMemcpyAsync(out + 32768, hc, 4 * 64 * 768 * sizeof(float),
                        cudaMemcpyDeviceToDevice, 0);
    }
}

// round 16
// speedup vs baseline: 1.4519x; 1.2149x over previous
#include <cuda_runtime.h>
#include <cuda_fp16.h>
#include <cstdint>

#define HID 768
#define TSEQ 1024
#define BATCH 64
#define NCTA 128

// ---------------- device scratch ----------------
// xp scratch: [d][t][us(32)][bg(2)][b(32)][96] fp32 (1.61 GB) — CTA-contiguous
__device__ float g_xp[402653184];
__device__ __half g_x16[64 * 1024 * 512];
__device__ __half g_wx16[6144 * 512];
__device__ __half g_h16[2 * 2 * BATCH * HID];   // h double buffer fp16
__device__ float g_hc[4 * BATCH * HID];         // hf, cf, hb, cb fp32
// central-atomic barrier per (dir, batch-group): 4 groups of 32 CTAs (128B padded)
__device__ unsigned g_cnt4[4 * 32];
__device__ unsigned g_gen4[4 * 32];

__global__ void init_kernel() {
    int i = threadIdx.x;
    if (i < 4 * 32) { g_cnt4[i] = 0; g_gen4[i] = 0; }
}

// ---------------- generic helpers ----------------
__device__ __forceinline__ void cp16(void* sdst, const void* gsrc) {
    unsigned sa = (unsigned)__cvta_generic_to_shared(sdst);
    asm volatile("cp.async.cg.shared.global [%0], [%1], 16;" :: "r"(sa), "l"(gsrc));
}
__device__ __forceinline__ void cp_commit() { asm volatile("cp.async.commit_group;"); }
template <int N> __device__ __forceinline__ void cp_wait() {
    asm volatile("cp.async.wait_group %0;" :: "n"(N));
}
__device__ __forceinline__ void ldsm4(unsigned& r0, unsigned& r1, unsigned& r2,
                                      unsigned& r3, const void* p) {
    unsigned a = (unsigned)__cvta_generic_to_shared(p);
    asm volatile("ldmatrix.sync.aligned.m8n8.x4.shared.b16 {%0,%1,%2,%3}, [%4];"
                 : "=r"(r0), "=r"(r1), "=r"(r2), "=r"(r3) : "r"(a));
}
__device__ __forceinline__ void mma16(float* acc, unsigned a0, unsigned a1,
                                      unsigned a2, unsigned a3, unsigned b0, unsigned b1) {
    asm volatile(
        "mma.sync.aligned.m16n8k16.row.col.f32.f16.f16.f32 "
        "{%0,%1,%2,%3},{%4,%5,%6,%7},{%8,%9},{%0,%1,%2,%3};"
        : "+f"(acc[0]), "+f"(acc[1]), "+f"(acc[2]), "+f"(acc[3])
        : "r"(a0), "r"(a1), "r"(a2), "r"(a3), "r"(b0), "r"(b1));
}
__device__ __forceinline__ float tanhapx(float x) {
    float y;
    asm("tanh.approx.f32 %0, %1;" : "=f"(y) : "f"(x));
    return y;
}
__device__ __forceinline__ float sigmapx(float x) {
    return 0.5f + 0.5f * tanhapx(0.5f * x);
}
// ---- central-atomic barrier per (dir,batch-group): 32 arrivals ----
__device__ __forceinline__ void garrive(int bg) {
    __threadfence();
    __syncthreads();
    if (threadIdx.x == 0) {
        unsigned a = atomicAdd(&g_cnt4[bg * 32], 1u);
        if (a == 31u) {
            g_cnt4[bg * 32] = 0;
            __threadfence();
            atomicAdd(&g_gen4[bg * 32], 1u);
        }
    }
}
__device__ __forceinline__ void gwait(int bg, unsigned target) {
    if (threadIdx.x == 0) {
        unsigned v;
        do {
            asm volatile("ld.acquire.gpu.u32 %0, [%1];" : "=r"(v) : "l"(&g_gen4[bg * 32]));
        } while (v < target);
    }
    __syncthreads();
}

// ---------------- merged fp32 -> fp16 conversion (X, Wxf, Wxb in one launch) -----
#define CONV_N1 8388608
#define CONV_N2 393216
__global__ __launch_bounds__(1024) void conv_kernel(
    const float4* __restrict__ X, const float4* __restrict__ Wxf,
    const float4* __restrict__ Wxb)
{
    int i = blockIdx.x * 1024 + threadIdx.x;
    const float4* s;
    __half2* dbase;
    int li;
    if (i < CONV_N1) {
        s = X; dbase = (__half2*)g_x16; li = i;
    } else if (i < CONV_N1 + CONV_N2) {
        s = Wxf; dbase = (__half2*)g_wx16; li = i - CONV_N1;
    } else if (i < CONV_N1 + 2 * CONV_N2) {
        s = Wxb; dbase = (__half2*)g_wx16 + 2 * CONV_N2; li = i - CONV_N1 - CONV_N2;
    } else return;
    float4 v = s[li];
    dbase[2 * li + 0] = __floats2half2_rn(v.x, v.y);
    dbase[2 * li + 1] = __floats2half2_rn(v.z, v.w);
}

// ================= Phase A: xp = x @ [Wxf;Wxb]^T + bias (fp16 mma.sync) ===========
__global__ __launch_bounds__(256, 2) void xproj_kernel(
    const float* __restrict__ bf, const float* __restrict__ bb)
{
    extern __shared__ __half sm16[];
    __half* As = sm16;
    __half* Bs = sm16 + 2 * 128 * 40;
    const int tid = threadIdx.x;
    const int bn = blockIdx.x, bm = blockIdx.y;
    const int warp = tid >> 5, lane = tid & 31;
    const int wm = warp >> 1, wn = warp & 1;
    const int gq = lane >> 2, tig = lane & 3;
    const int lrow = lane & 15, lcol = (lane >> 4) << 3;

    auto stage = [&](int buf, int k0) {
        __half* Ad = As + buf * (128 * 40);
        __half* Bd = Bs + buf * (64 * 40);
#pragma unroll
        for (int j = 0; j < 2; ++j) {
            int idx = j * 256 + tid;
            int r = idx >> 2, q = idx & 3;
            cp16(Ad + r * 40 + q * 8, g_x16 + (size_t)(bm * 128 + r) * 512 + k0 + q * 8);
        }
        {
            int r = tid >> 2, q = tid & 3;
            cp16(Bd + r * 40 + q * 8, g_wx16 + (size_t)(bn * 64 + r) * 512 + k0 + q * 8);
        }
        cp_commit();
    };

    float acc[2][4][4];
#pragma unroll
    for (int a = 0; a < 2; ++a)
#pragma unroll
        for (int b = 0; b < 4; ++b)
#pragma unroll
            for (int c = 0; c < 4; ++c) acc[a][b][c] = 0.f;

    stage(0, 0);
#pragma unroll 1
    for (int it = 0; it < 16; ++it) {
        if (it < 15) { stage((it + 1) & 1, (it + 1) * 32); cp_wait<1>(); }
        else { cp_wait<0>(); }
        __syncthreads();
        const __half* Ab = As + (it & 1) * (128 * 40);
        const __half* Bb = Bs + (it & 1) * (64 * 40);
#pragma unroll
        for (int k16 = 0; k16 < 2; ++k16) {
            int k0 = k16 * 16;
            unsigned a[2][4];
#pragma unroll
            for (int mt = 0; mt < 2; ++mt)
                ldsm4(a[mt][0], a[mt][1], a[mt][2], a[mt][3],
                      Ab + (wm * 32 + mt * 16 + lrow) * 40 + k0 + lcol);
#pragma unroll
            for (int np = 0; np < 2; ++np) {
                unsigned r0, r1, r2, r3;
                ldsm4(r0, r1, r2, r3,
                      Bb + (wn * 32 + np * 16 + lrow) * 40 + k0 + lcol);
                mma16(acc[0][np * 2 + 0], a[0][0], a[0][1], a[0][2], a[0][3], r0, r2);
                mma16(acc[0][np * 2 + 1], a[0][0], a[0][1], a[0][2], a[0][3], r1, r3);
                mma16(acc[1][np * 2 + 0], a[1][0], a[1][1], a[1][2], a[1][3], r0, r2);
                mma16(acc[1][np * 2 + 1], a[1][0], a[1][1], a[1][2], a[1][3], r1, r3);
            }
        }
        __syncthreads();
    }
    // epilogue: bias + time-reversal scatter into g_xp[d][t][us32][bg][b32][96]
#pragma unroll
    for (int mt = 0; mt < 2; ++mt) {
#pragma unroll
        for (int r = 0; r < 2; ++r) {
            int m = bm * 128 + wm * 32 + mt * 16 + gq + r * 8;
            int b = m >> 10;
            int tx = m & 1023;
            int bg = b >> 5, bl = b & 31;
#pragma unroll
            for (int nt = 0; nt < 4; ++nt) {
                int n0 = bn * 64 + wn * 32 + nt * 8 + tig * 2;
                int d = (n0 >= 3072) ? 1 : 0;
                int g = n0 - d * 3072;
                int gate = g / 768;
                int unit = g - gate * 768;
                int us2 = unit / 24;
                int uu = unit - us2 * 24;
                int t = d ? (1023 - tx) : tx;
                float2 v;
                v.x = acc[mt][nt][r * 2 + 0] + (d ? bb[g] : bf[g]);
                v.y = acc[mt][nt][r * 2 + 1] + (d ? bb[g + 1] : bf[g + 1]);
                size_t addr = ((((size_t)(d * 1024 + t) * 32 + us2) * 2 + bg) * 32 + bl) * 96
                            + gate * 24 + uu;
                *(float2*)(g_xp + addr) = v;
            }
        }
    }
}

// ================= Phase B: persistent recurrence, batch-group partitioned ========
// 128 CTAs x 256 thr. CTA: d = cid>>6, g = (cid>>5)&1 (32-batch group),
// us = cid&31 -> units [us*24, us*24+24) (96 gate rows). Barrier spans 32 CTAs.
// MMA: M=32 (batch), N=96 (gate rows), K=768. Warp: mw = w&1 (16-row m-tile),
// ng = (w>>1)&1 (6 nt), kp = w>>2 (K-half). 144 HMMA/warp.
// smem: Wf 147456 | A_s 32x776 49664 | zx 2 x 32x100 f32 25600. Total 222720.
#define RSMEM_TOTAL 222720
__global__ __launch_bounds__(256, 1) void recur_kernel(
    const float* __restrict__ Whf, const float* __restrict__ Whb)
{
    extern __shared__ char smraw[];
    __half2* Wf2 = (__half2*)smraw;                        // 18432 uint2 = 147456 B
    __half* A_s  = (__half*)(smraw + 147456);              // 32 x 776
    float*  zbuf = (float*)(smraw + 147456 + 49664);       // 2 x 32 x 100

    const int tid = threadIdx.x;
    const int warp = tid >> 5, lane = tid & 31;
    const int gq = lane >> 2, tig = lane & 3;
    const int lrow = lane & 15, lcol = (lane >> 4) << 3;
    const int mw = warp & 1;
    const int ng = (warp >> 1) & 1;
    const int kp = warp >> 2;
    const int cid = blockIdx.x;
    const int d = cid >> 6, g = (cid >> 5) & 1, us = cid & 31;
    const int bg = d * 2 + g;          // barrier group
    const float* Wh = d ? Whb : Whf;

    // --- pre-arrange resident weight fragments (once): 48 chunks x 12 nt ---
    for (int idx = tid; idx < 18432; idx += 256) {
        int c = idx / 384;            // k16 chunk 0..47
        int r = idx % 384;
        int nt = r >> 5;              // 0..11
        int ln = r & 31;
        int fq = ln >> 2, ft = ln & 3;
        int gr = nt * 8 + fq;         // gate row 0..95
        int gb = gr / 24, uu = gr % 24;
        const float* w = Wh + (size_t)(gb * 768 + us * 24 + uu) * 768 + c * 16 + ft * 2;
        Wf2[idx * 2 + 0] = __floats2half2_rn(w[0], w[1]);
        Wf2[idx * 2 + 1] = __floats2half2_rn(w[8], w[9]);
    }
    // zero h buf0 for my slice (32 batches x 24 units)
    for (int v = tid; v < 768; v += 256) {
        int b = v / 24, uu = v % 24;
        g_h16[((size_t)(0 * 2 + d) * 64 + g * 32 + b) * 768 + us * 24 + uu] = __float2half(0.f);
    }
    // prefetch xp(0) into zbuf[0]
    {
        const float* xp0 = g_xp + (((size_t)(d * 1024 + 0) * 32 + us) * 2 + g) * 32 * 96;
#pragma unroll
        for (int j = 0; j < 3; ++j) {
            int idx = j * 256 + tid;
            int b = idx / 24, q = idx % 24;
            cp16(zbuf + b * 100 + q * 4, xp0 + b * 96 + q * 4);
        }
        cp_commit();
    }
    float cc[3];
#pragma unroll
    for (int j = 0; j < 3; ++j) cc[j] = 0.f;

    garrive(bg);   // h(0) published

    const uint2* Wfu = (const uint2*)Wf2;

#pragma unroll 1
    for (int t = 0; t < 1024; ++t) {
        gwait(bg, (unsigned)(t + 1));   // group's h(t) published
        const __half* hcur = g_h16 + (size_t)((t & 1) * 2 + d) * BATCH * HID
                           + (size_t)g * 32 * HID;

        // --- stage h: 32 rows x 768 halves, 12 cp16 per thread ---
#pragma unroll
        for (int j = 0; j < 12; ++j) {
            int idx = j * 256 + tid;
            int b = idx / 96, q = idx % 96;
            cp16(A_s + b * 776 + q * 8, hcur + (size_t)b * 768 + q * 8);
        }
        cp_commit();
        cp_wait<0>();    // h staged (and xp(t) prefetch from earlier)
        __syncthreads();

        // --- MMA: 24 k16 chunks for this warp's K-half, 6 nt, 1 m-tile ---
        float acc[6][4];
#pragma unroll
        for (int a = 0; a < 6; ++a)
#pragma unroll
            for (int b = 0; b < 4; ++b) acc[a][b] = 0.f;

#pragma unroll 2
        for (int cnk = 0; cnk < 24; ++cnk) {
            int c = kp * 24 + cnk;
            int k0 = c * 16;
            unsigned a0, a1, a2, a3;
            ldsm4(a0, a1, a2, a3, A_s + (mw * 16 + lrow) * 776 + k0 + lcol);
#pragma unroll
            for (int nt = 0; nt < 6; ++nt) {
                uint2 bv = Wfu[(c * 12 + ng * 6 + nt) * 32 + lane];
                mma16(acc[nt], a0, a1, a2, a3, bv.x, bv.y);
            }
        }

        // --- two-pass reduction: RMW partials onto zx (which holds xp) ---
        float* zx = zbuf + (t & 1) * 3200;
        if (kp == 0) {
#pragma unroll
            for (int nt = 0; nt < 6; ++nt) {
                int row = mw * 16 + gq;
                int col = ng * 48 + nt * 8 + 2 * tig;
                float2* p0 = (float2*)(zx + row * 100 + col);
                float2* p1 = (float2*)(zx + (row + 8) * 100 + col);
                float2 v0 = *p0; v0.x += acc[nt][0]; v0.y += acc[nt][1]; *p0 = v0;
                float2 v1 = *p1; v1.x += acc[nt][2]; v1.y += acc[nt][3]; *p1 = v1;
            }
        }
        __syncthreads();
        if (kp == 1) {
#pragma unroll
            for (int nt = 0; nt < 6; ++nt) {
                int row = mw * 16 + gq;
                int col = ng * 48 + nt * 8 + 2 * tig;
                float2* p0 = (float2*)(zx + row * 100 + col);
                float2* p1 = (float2*)(zx + (row + 8) * 100 + col);
                float2 v0 = *p0; v0.x += acc[nt][0]; v0.y += acc[nt][1]; *p0 = v0;
                float2 v1 = *p1; v1.x += acc[nt][2]; v1.y += acc[nt][3]; *p1 = v1;
            }
        }
        __syncthreads();

        // --- pointwise: 3 (b,unit) pairs per thread ---
        int nb = (t + 1) & 1;
        __half* hdst = g_h16 + (size_t)(nb * 2 + d) * BATCH * HID + (size_t)g * 32 * HID;
#pragma unroll
        for (int j = 0; j < 3; ++j) {
            int idx = j * 256 + tid;
            int b = idx / 24, uu = idx % 24;
            const float* zr = zx + b * 100;
            float f = sigmapx(zr[uu]);
            float i = sigmapx(zr[24 + uu]);
            float gg = tanhapx(zr[48 + uu]);
            float o = sigmapx(zr[72 + uu]);
            float c = f * cc[j] + i * gg;
            cc[j] = c;
            float h = o * tanhapx(c);
            hdst[(size_t)b * 768 + us * 24 + uu] = __float2half_rn(h);
            if (t == 1023) {
                int unit = us * 24 + uu;
                int bglob = g * 32 + b;
                g_hc[((size_t)(d * 2 + 0) * 64 + bglob) * 768 + unit] = h;
                g_hc[((size_t)(d * 2 + 1) * 64 + bglob) * 768 + unit] = c;
            }
        }

        garrive(bg);   // h(t+1) published

        // --- prefetch xp(t+1) during barrier propagation ---
        if (t < 1023) {
            const float* xpn = g_xp + (((size_t)(d * 1024 + t + 1) * 32 + us) * 2 + g) * 32 * 96;
            float* zn = zbuf + ((t + 1) & 1) * 3200;
#pragma unroll
            for (int j = 0; j < 3; ++j) {
                int idx = j * 256 + tid;
                int b = idx / 24, q = idx % 24;
                cp16(zn + b * 100 + q * 4, xpn + b * 96 + q * 4);
            }
            cp_commit();
        }
    }
}

// ================= Phase C: out = [hf|hb] @ Why^T + by =================
__global__ __launch_bounds__(256) void outproj_kernel(
    const float* __restrict__ Why, const float* __restrict__ by,
    float* __restrict__ out)
{
    int w = blockIdx.x * 8 + (threadIdx.x >> 5);
    int lane = threadIdx.x & 31;
    int b = w >> 9, o = w & 511;
    const float* hf = g_hc + (size_t)b * 768;
    const float* hb = g_hc + 98304 + (size_t)b * 768;
    const float* wr = Why + (size_t)o * 1536;
    float s = 0.f;
    for (int k = lane; k < 768; k += 32) s += hf[k] * wr[k];
    for (int k = lane; k < 768; k += 32) s += hb[k] * wr[768 + k];
#pragma unroll
    for (int off = 16; off; off >>= 1) s += __shfl_xor_sync(0xffffffffu, s, off);
    if (lane == 0) out[(size_t)b * 512 + o] = s + by[o];
}

// ================= launch =================
extern "C" void kernel_launch(void* const* d_in, const int* in_sizes, int n_in,
                              void* d_out, int out_size) {
    const float* X   = (const float*)d_in[0];
    const float* Wxf = (const float*)d_in[1];
    const float* Whf = (const float*)d_in[2];
    const float* bf  = (const float*)d_in[3];
    const float* Wxb = (const float*)d_in[4];
    const float* Whb = (const float*)d_in[5];
    const float* bb  = (const float*)d_in[6];
    const float* Why = (const float*)d_in[7];
    const float* by  = (const float*)d_in[8];
    float* out = (float*)d_out;

    cudaFuncSetAttribute(xproj_kernel, cudaFuncAttributeMaxDynamicSharedMemorySize, 30720);
    cudaFuncSetAttribute(recur_kernel, cudaFuncAttributeMaxDynamicSharedMemorySize, RSMEM_TOTAL);

    init_kernel<<<1, 256>>>();
    conv_kernel<<<8960, 1024>>>((const float4*)X, (const float4*)Wxf, (const float4*)Wxb);
    xproj_kernel<<<dim3(96, 512), 256, 30720>>>(bf, bb);
    recur_kernel<<<NCTA, 256, RSMEM_TOTAL>>>(Whf, Whb);
    outproj_kernel<<<4096, 256>>>(Why, by, out);

    if (out_size >= 229376) {
        void* hc = nullptr;
        cudaGetSymbolAddress(&hc, g_hc);
        cudaMemcpyAsync(out + 32768, hc, 4 * 64 * 768 * sizeof(float),
                        cudaMemcpyDeviceToDevice, 0);
    }
}

// round 17
// speedup vs baseline: 1.7018x; 1.1721x over previous
#include <cuda_runtime.h>
#include <cuda_fp16.h>
#include <cstdint>

#define HID 768
#define TSEQ 1024
#define BATCH 64
#define NCTA 128

// ---------------- device scratch ----------------
// xp scratch: [d][t][us(32)][bg(2)][b(32)][96] fp32 (1.61 GB) — CTA-contiguous
__device__ float g_xp[402653184];
__device__ __half g_x16[64 * 1024 * 512];
__device__ __half g_wx16[6144 * 512];
__device__ __half g_h16[2 * 2 * BATCH * HID];   // h double buffer fp16
__device__ float g_hc[4 * BATCH * HID];         // hf, cf, hb, cb fp32
// monotonic barrier counters per (dir, batch-group): 4 groups of 32 CTAs (128B padded)
__device__ unsigned g_cnt4[4 * 32];

__global__ void init_kernel() {
    int i = threadIdx.x;
    if (i < 4 * 32) g_cnt4[i] = 0;
}

// ---------------- generic helpers ----------------
__device__ __forceinline__ void cp16(void* sdst, const void* gsrc) {
    unsigned sa = (unsigned)__cvta_generic_to_shared(sdst);
    asm volatile("cp.async.cg.shared.global [%0], [%1], 16;" :: "r"(sa), "l"(gsrc));
}
__device__ __forceinline__ void cp_commit() { asm volatile("cp.async.commit_group;"); }
template <int N> __device__ __forceinline__ void cp_wait() {
    asm volatile("cp.async.wait_group %0;" :: "n"(N));
}
__device__ __forceinline__ void ldsm4(unsigned& r0, unsigned& r1, unsigned& r2,
                                      unsigned& r3, const void* p) {
    unsigned a = (unsigned)__cvta_generic_to_shared(p);
    asm volatile("ldmatrix.sync.aligned.m8n8.x4.shared.b16 {%0,%1,%2,%3}, [%4];"
                 : "=r"(r0), "=r"(r1), "=r"(r2), "=r"(r3) : "r"(a));
}
__device__ __forceinline__ void mma16(float* acc, unsigned a0, unsigned a1,
                                      unsigned a2, unsigned a3, unsigned b0, unsigned b1) {
    asm volatile(
        "mma.sync.aligned.m16n8k16.row.col.f32.f16.f16.f32 "
        "{%0,%1,%2,%3},{%4,%5,%6,%7},{%8,%9},{%0,%1,%2,%3};"
        : "+f"(acc[0]), "+f"(acc[1]), "+f"(acc[2]), "+f"(acc[3])
        : "r"(a0), "r"(a1), "r"(a2), "r"(a3), "r"(b0), "r"(b1));
}
__device__ __forceinline__ float tanhapx(float x) {
    float y;
    asm("tanh.approx.f32 %0, %1;" : "=f"(y) : "f"(x));
    return y;
}
__device__ __forceinline__ float sigmapx(float x) {
    return 0.5f + 0.5f * tanhapx(0.5f * x);
}
// ---- monotonic-counter barrier per (dir,batch-group): 32 arrivals ----
// arrive: fire-and-forget release-RED (no round trip, no fence, no gen hop)
__device__ __forceinline__ void garrive(int bg) {
    __syncthreads();
    if (threadIdx.x == 0) {
        asm volatile("red.release.gpu.global.add.u32 [%0], %1;"
                     :: "l"(g_cnt4 + bg * 32), "r"(1u) : "memory");
    }
}
// wait: poll the same counter for >= 32*step
__device__ __forceinline__ void gwait(int bg, unsigned target) {
    if (threadIdx.x == 0) {
        unsigned v;
        do {
            asm volatile("ld.acquire.gpu.u32 %0, [%1];" : "=r"(v) : "l"(g_cnt4 + bg * 32) : "memory");
        } while (v < target);
    }
    __syncthreads();
}

// ---------------- merged fp32 -> fp16 conversion (X, Wxf, Wxb in one launch) -----
#define CONV_N1 8388608
#define CONV_N2 393216
__global__ __launch_bounds__(1024) void conv_kernel(
    const float4* __restrict__ X, const float4* __restrict__ Wxf,
    const float4* __restrict__ Wxb)
{
    int i = blockIdx.x * 1024 + threadIdx.x;
    const float4* s;
    __half2* dbase;
    int li;
    if (i < CONV_N1) {
        s = X; dbase = (__half2*)g_x16; li = i;
    } else if (i < CONV_N1 + CONV_N2) {
        s = Wxf; dbase = (__half2*)g_wx16; li = i - CONV_N1;
    } else if (i < CONV_N1 + 2 * CONV_N2) {
        s = Wxb; dbase = (__half2*)g_wx16 + 2 * CONV_N2; li = i - CONV_N1 - CONV_N2;
    } else return;
    float4 v = s[li];
    dbase[2 * li + 0] = __floats2half2_rn(v.x, v.y);
    dbase[2 * li + 1] = __floats2half2_rn(v.z, v.w);
}

// ================= Phase A: xp = x @ [Wxf;Wxb]^T + bias (fp16 mma.sync) ===========
__global__ __launch_bounds__(256, 2) void xproj_kernel(
    const float* __restrict__ bf, const float* __restrict__ bb)
{
    extern __shared__ __half sm16[];
    __half* As = sm16;
    __half* Bs = sm16 + 2 * 128 * 40;
    const int tid = threadIdx.x;
    const int bn = blockIdx.x, bm = blockIdx.y;
    const int warp = tid >> 5, lane = tid & 31;
    const int wm = warp >> 1, wn = warp & 1;
    const int gq = lane >> 2, tig = lane & 3;
    const int lrow = lane & 15, lcol = (lane >> 4) << 3;

    auto stage = [&](int buf, int k0) {
        __half* Ad = As + buf * (128 * 40);
        __half* Bd = Bs + buf * (64 * 40);
#pragma unroll
        for (int j = 0; j < 2; ++j) {
            int idx = j * 256 + tid;
            int r = idx >> 2, q = idx & 3;
            cp16(Ad + r * 40 + q * 8, g_x16 + (size_t)(bm * 128 + r) * 512 + k0 + q * 8);
        }
        {
            int r = tid >> 2, q = tid & 3;
            cp16(Bd + r * 40 + q * 8, g_wx16 + (size_t)(bn * 64 + r) * 512 + k0 + q * 8);
        }
        cp_commit();
    };

    float acc[2][4][4];
#pragma unroll
    for (int a = 0; a < 2; ++a)
#pragma unroll
        for (int b = 0; b < 4; ++b)
#pragma unroll
            for (int c = 0; c < 4; ++c) acc[a][b][c] = 0.f;

    stage(0, 0);
#pragma unroll 1
    for (int it = 0; it < 16; ++it) {
        if (it < 15) { stage((it + 1) & 1, (it + 1) * 32); cp_wait<1>(); }
        else { cp_wait<0>(); }
        __syncthreads();
        const __half* Ab = As + (it & 1) * (128 * 40);
        const __half* Bb = Bs + (it & 1) * (64 * 40);
#pragma unroll
        for (int k16 = 0; k16 < 2; ++k16) {
            int k0 = k16 * 16;
            unsigned a[2][4];
#pragma unroll
            for (int mt = 0; mt < 2; ++mt)
                ldsm4(a[mt][0], a[mt][1], a[mt][2], a[mt][3],
                      Ab + (wm * 32 + mt * 16 + lrow) * 40 + k0 + lcol);
#pragma unroll
            for (int np = 0; np < 2; ++np) {
                unsigned r0, r1, r2, r3;
                ldsm4(r0, r1, r2, r3,
                      Bb + (wn * 32 + np * 16 + lrow) * 40 + k0 + lcol);
                mma16(acc[0][np * 2 + 0], a[0][0], a[0][1], a[0][2], a[0][3], r0, r2);
                mma16(acc[0][np * 2 + 1], a[0][0], a[0][1], a[0][2], a[0][3], r1, r3);
                mma16(acc[1][np * 2 + 0], a[1][0], a[1][1], a[1][2], a[1][3], r0, r2);
                mma16(acc[1][np * 2 + 1], a[1][0], a[1][1], a[1][2], a[1][3], r1, r3);
            }
        }
        __syncthreads();
    }
    // epilogue: bias + time-reversal scatter into g_xp[d][t][us32][bg][b32][96]
#pragma unroll
    for (int mt = 0; mt < 2; ++mt) {
#pragma unroll
        for (int r = 0; r < 2; ++r) {
            int m = bm * 128 + wm * 32 + mt * 16 + gq + r * 8;
            int b = m >> 10;
            int tx = m & 1023;
            int bg = b >> 5, bl = b & 31;
#pragma unroll
            for (int nt = 0; nt < 4; ++nt) {
                int n0 = bn * 64 + wn * 32 + nt * 8 + tig * 2;
                int d = (n0 >= 3072) ? 1 : 0;
                int g = n0 - d * 3072;
                int gate = g / 768;
                int unit = g - gate * 768;
                int us2 = unit / 24;
                int uu = unit - us2 * 24;
                int t = d ? (1023 - tx) : tx;
                float2 v;
                v.x = acc[mt][nt][r * 2 + 0] + (d ? bb[g] : bf[g]);
                v.y = acc[mt][nt][r * 2 + 1] + (d ? bb[g + 1] : bf[g + 1]);
                size_t addr = ((((size_t)(d * 1024 + t) * 32 + us2) * 2 + bg) * 32 + bl) * 96
                            + gate * 24 + uu;
                *(float2*)(g_xp + addr) = v;
            }
        }
    }
}

// ================= Phase B: persistent recurrence, batch-group partitioned ========
// 128 CTAs x 256 thr. CTA: d = cid>>6, g = (cid>>5)&1 (32-batch group),
// us = cid&31 -> units [us*24, us*24+24) (96 gate rows). Barrier spans 32 CTAs.
// MMA: M=32 (batch), N=96 (gate rows), K=768. Warp: mw = w&1 (16-row m-tile),
// ng = (w>>1)&1 (6 nt), kp = w>>2 (K-half). 144 HMMA/warp.
// smem: Wf 147456 | A_s 32x776 49664 | zx 2 x 32x100 f32 25600. Total 222720.
#define RSMEM_TOTAL 222720
__global__ __launch_bounds__(256, 1) void recur_kernel(
    const float* __restrict__ Whf, const float* __restrict__ Whb)
{
    extern __shared__ char smraw[];
    __half2* Wf2 = (__half2*)smraw;                        // 18432 uint2 = 147456 B
    __half* A_s  = (__half*)(smraw + 147456);              // 32 x 776
    float*  zbuf = (float*)(smraw + 147456 + 49664);       // 2 x 32 x 100

    const int tid = threadIdx.x;
    const int warp = tid >> 5, lane = tid & 31;
    const int gq = lane >> 2, tig = lane & 3;
    const int lrow = lane & 15, lcol = (lane >> 4) << 3;
    const int mw = warp & 1;
    const int ng = (warp >> 1) & 1;
    const int kp = warp >> 2;
    const int cid = blockIdx.x;
    const int d = cid >> 6, g = (cid >> 5) & 1, us = cid & 31;
    const int bg = d * 2 + g;          // barrier group
    const float* Wh = d ? Whb : Whf;

    // --- pre-arrange resident weight fragments (once): 48 chunks x 12 nt ---
    for (int idx = tid; idx < 18432; idx += 256) {
        int c = idx / 384;            // k16 chunk 0..47
        int r = idx % 384;
        int nt = r >> 5;              // 0..11
        int ln = r & 31;
        int fq = ln >> 2, ft = ln & 3;
        int gr = nt * 8 + fq;         // gate row 0..95
        int gb = gr / 24, uu = gr % 24;
        const float* w = Wh + (size_t)(gb * 768 + us * 24 + uu) * 768 + c * 16 + ft * 2;
        Wf2[idx * 2 + 0] = __floats2half2_rn(w[0], w[1]);
        Wf2[idx * 2 + 1] = __floats2half2_rn(w[8], w[9]);
    }
    // zero h buf0 for my slice (32 batches x 24 units)
    for (int v = tid; v < 768; v += 256) {
        int b = v / 24, uu = v % 24;
        g_h16[((size_t)(0 * 2 + d) * 64 + g * 32 + b) * 768 + us * 24 + uu] = __float2half(0.f);
    }
    // prefetch xp(0) into zbuf[0]
    {
        const float* xp0 = g_xp + (((size_t)(d * 1024 + 0) * 32 + us) * 2 + g) * 32 * 96;
#pragma unroll
        for (int j = 0; j < 3; ++j) {
            int idx = j * 256 + tid;
            int b = idx / 24, q = idx % 24;
            cp16(zbuf + b * 100 + q * 4, xp0 + b * 96 + q * 4);
        }
        cp_commit();
    }
    float cc[3];
#pragma unroll
    for (int j = 0; j < 3; ++j) cc[j] = 0.f;

    __threadfence();   // make h zeros visible before first arrive
    garrive(bg);       // h(0) published

    const uint2* Wfu = (const uint2*)Wf2;

#pragma unroll 1
    for (int t = 0; t < 1024; ++t) {
        gwait(bg, 32u * (unsigned)(t + 1));   // group's h(t) published
        const __half* hcur = g_h16 + (size_t)((t & 1) * 2 + d) * BATCH * HID
                           + (size_t)g * 32 * HID;

        // --- stage h: 32 rows x 768 halves, 12 cp16 per thread ---
#pragma unroll
        for (int j = 0; j < 12; ++j) {
            int idx = j * 256 + tid;
            int b = idx / 96, q = idx % 96;
            cp16(A_s + b * 776 + q * 8, hcur + (size_t)b * 768 + q * 8);
        }
        cp_commit();
        cp_wait<0>();    // h staged (and xp(t) prefetch from earlier)
        __syncthreads();

        // --- MMA: 24 k16 chunks for this warp's K-half, 6 nt, 1 m-tile ---
        float acc[6][4];
#pragma unroll
        for (int a = 0; a < 6; ++a)
#pragma unroll
            for (int b = 0; b < 4; ++b) acc[a][b] = 0.f;

#pragma unroll 2
        for (int cnk = 0; cnk < 24; ++cnk) {
            int c = kp * 24 + cnk;
            int k0 = c * 16;
            unsigned a0, a1, a2, a3;
            ldsm4(a0, a1, a2, a3, A_s + (mw * 16 + lrow) * 776 + k0 + lcol);
#pragma unroll
            for (int nt = 0; nt < 6; ++nt) {
                uint2 bv = Wfu[(c * 12 + ng * 6 + nt) * 32 + lane];
                mma16(acc[nt], a0, a1, a2, a3, bv.x, bv.y);
            }
        }

        // --- two-pass deterministic reduction: RMW partials onto zx (holds xp) ---
        float* zx = zbuf + (t & 1) * 3200;
        if (kp == 0) {
#pragma unroll
            for (int nt = 0; nt < 6; ++nt) {
                int row = mw * 16 + gq;
                int col = ng * 48 + nt * 8 + 2 * tig;
                float2* p0 = (float2*)(zx + row * 100 + col);
                float2* p1 = (float2*)(zx + (row + 8) * 100 + col);
                float2 v0 = *p0; v0.x += acc[nt][0]; v0.y += acc[nt][1]; *p0 = v0;
                float2 v1 = *p1; v1.x += acc[nt][2]; v1.y += acc[nt][3]; *p1 = v1;
            }
        }
        __syncthreads();
        if (kp == 1) {
#pragma unroll
            for (int nt = 0; nt < 6; ++nt) {
                int row = mw * 16 + gq;
                int col = ng * 48 + nt * 8 + 2 * tig;
                float2* p0 = (float2*)(zx + row * 100 + col);
                float2* p1 = (float2*)(zx + (row + 8) * 100 + col);
                float2 v0 = *p0; v0.x += acc[nt][0]; v0.y += acc[nt][1]; *p0 = v0;
                float2 v1 = *p1; v1.x += acc[nt][2]; v1.y += acc[nt][3]; *p1 = v1;
            }
        }
        __syncthreads();

        // --- pointwise: 3 (b,unit) pairs per thread ---
        int nb = (t + 1) & 1;
        __half* hdst = g_h16 + (size_t)(nb * 2 + d) * BATCH * HID + (size_t)g * 32 * HID;
#pragma unroll
        for (int j = 0; j < 3; ++j) {
            int idx = j * 256 + tid;
            int b = idx / 24, uu = idx % 24;
            const float* zr = zx + b * 100;
            float f = sigmapx(zr[uu]);
            float i = sigmapx(zr[24 + uu]);
            float gg = tanhapx(zr[48 + uu]);
            float o = sigmapx(zr[72 + uu]);
            float c = f * cc[j] + i * gg;
            cc[j] = c;
            float h = o * tanhapx(c);
            hdst[(size_t)b * 768 + us * 24 + uu] = __float2half_rn(h);
            if (t == 1023) {
                int unit = us * 24 + uu;
                int bglob = g * 32 + b;
                g_hc[((size_t)(d * 2 + 0) * 64 + bglob) * 768 + unit] = h;
                g_hc[((size_t)(d * 2 + 1) * 64 + bglob) * 768 + unit] = c;
            }
        }

        garrive(bg);   // h(t+1) published (release-RED, fire-and-forget)

        // --- prefetch xp(t+1) during barrier propagation ---
        if (t < 1023) {
            const float* xpn = g_xp + (((size_t)(d * 1024 + t + 1) * 32 + us) * 2 + g) * 32 * 96;
            float* zn = zbuf + ((t + 1) & 1) * 3200;
#pragma unroll
            for (int j = 0; j < 3; ++j) {
                int idx = j * 256 + tid;
                int b = idx / 24, q = idx % 24;
                cp16(zn + b * 100 + q * 4, xpn + b * 96 + q * 4);
            }
            cp_commit();
        }
    }
}

// ================= Phase C: out = [hf|hb] @ Why^T + by =================
__global__ __launch_bounds__(256) void outproj_kernel(
    const float* __restrict__ Why, const float* __restrict__ by,
    float* __restrict__ out)
{
    int w = blockIdx.x * 8 + (threadIdx.x >> 5);
    int lane = threadIdx.x & 31;
    int b = w >> 9, o = w & 511;
    const float* hf = g_hc + (size_t)b * 768;
    const float* hb = g_hc + 98304 + (size_t)b * 768;
    const float* wr = Why + (size_t)o * 1536;
    float s = 0.f;
    for (int k = lane; k < 768; k += 32) s += hf[k] * wr[k];
    for (int k = lane; k < 768; k += 32) s += hb[k] * wr[768 + k];
#pragma unroll
    for (int off = 16; off; off >>= 1) s += __shfl_xor_sync(0xffffffffu, s, off);
    if (lane == 0) out[(size_t)b * 512 + o] = s + by[o];
}

// ================= launch =================
extern "C" void kernel_launch(void* const* d_in, const int* in_sizes, int n_in,
                              void* d_out, int out_size) {
    const float* X   = (const float*)d_in[0];
    const float* Wxf = (const float*)d_in[1];
    const float* Whf = (const float*)d_in[2];
    const float* bf  = (const float*)d_in[3];
    const float* Wxb = (const float*)d_in[4];
    const float* Whb = (const float*)d_in[5];
    const float* bb  = (const float*)d_in[6];
    const float* Why = (const float*)d_in[7];
    const float* by  = (const float*)d_in[8];
    float* out = (float*)d_out;

    cudaFuncSetAttribute(xproj_kernel, cudaFuncAttributeMaxDynamicSharedMemorySize, 30720);
    cudaFuncSetAttribute(recur_kernel, cudaFuncAttributeMaxDynamicSharedMemorySize, RSMEM_TOTAL);

    init_kernel<<<1, 128>>>();
    conv_kernel<<<8960, 1024>>>((const float4*)X, (const float4*)Wxf, (const float4*)Wxb);
    xproj_kernel<<<dim3(96, 512), 256, 30720>>>(bf, bb);
    recur_kernel<<<NCTA, 256, RSMEM_TOTAL>>>(Whf, Whb);
    outproj_kernel<<<4096, 256>>>(Why, by, out);

    if (out_size >= 229376) {
        void* hc = nullptr;
        cudaGetSymbolAddress(&hc, g_hc);
        cudaMemcpyAsync(out + 32768, hc, 4 * 64 * 768 * sizeof(float),
                        cudaMemcpyDeviceToDevice, 0);
    }
}